// round 15
// baseline (speedup 1.0000x reference)
#include <cuda_runtime.h>
#include <cstdint>

// Problem shape (fixed by reference setup_inputs)
#define B_   16
#define Y_   32
#define HW_  65536                   // H*W = 256*256
#define NPIX (B_ * HW_)              // 1048576
#define THREADS 256
#define DIST_IND 7.0f

// Residency split: images [0,RES_B) pinned in L2 via evict_last (109 MB < 126 MB L2),
// images [RES_B,16) streamed with normal policy (25 MB -> evicts itself only).
#define RES_B   13
#define PPT_A   8                    // resident path: v8.b32 loads
#define PPT_B   4                    // streaming path: float4 loads
#define NPIX_A  (RES_B * HW_)                    // 851968
#define NBLK_A  (NPIX_A / (THREADS * PPT_A))     // 416
#define NPIX_B  ((B_ - RES_B) * HW_)             // 196608
#define NBLK_B  (NPIX_B / (THREADS * PPT_B))     // 192
#define GRID    (NBLK_A + NBLK_B)                // 608 = 152 SMs * 4

__device__ double g_partials[GRID];
__device__ unsigned int g_count = 0;

// 256-bit L2-pinned load (sm_103a: evict_last requires v8.b32).
__device__ __forceinline__ void ldg_el8(const float* p, float* v) {
    uint32_t r0, r1, r2, r3, r4, r5, r6, r7;
    asm("ld.global.nc.L2::evict_last.v8.b32 {%0,%1,%2,%3,%4,%5,%6,%7}, [%8];"
        : "=r"(r0), "=r"(r1), "=r"(r2), "=r"(r3),
          "=r"(r4), "=r"(r5), "=r"(r6), "=r"(r7)
        : "l"(p));
    v[0] = __uint_as_float(r0); v[1] = __uint_as_float(r1);
    v[2] = __uint_as_float(r2); v[3] = __uint_as_float(r3);
    v[4] = __uint_as_float(r4); v[5] = __uint_as_float(r5);
    v[6] = __uint_as_float(r6); v[7] = __uint_as_float(r7);
}

// Residual for the dominant f=0 case: one segment, n=32 (constants exact).
__device__ __forceinline__ float seg32(float sy, float sxy, float syy) {
    float cov = sxy - 15.5f * sy;
    float sl  = fminf(fmaxf(cov * (1.f / 2728.f), 0.f), 2.f);
    float c   = (sy - sl * 496.f) * 0.03125f;
    return syy - 2.f * sl * sxy - 2.f * c * sy
         + sl * sl * 10416.f + 2.f * sl * c * 496.f + c * c * 32.f;
}

// Exact general-segment residual (rare slow path).
__device__ __noinline__ float seg_gen(int n, float sy, float sxy, float syy) {
    if (n < 3) return 0.f;
    float nf  = (float)n;
    float sx  = 0.5f * nf * (nf - 1.f);
    float sxx = (nf - 1.f) * nf * (2.f * nf - 1.f) * (1.f / 6.f);
    float cov = sxy - sx * sy / nf;
    float var = sxx - sx * sx / nf;
    float vs  = (var > 0.f) ? var : 1.f;
    float sl  = fminf(fmaxf(cov / vs, 0.f), 2.f);
    float c   = (sy - sl * sx) / nf;
    return syy - 2.f * sl * sxy - 2.f * c * sy
         + sl * sl * sxx + 2.f * sl * c * sx + c * c * nf;
}

// Exact per-pixel correction: rescan column, replace f=0 value if f>0.
__device__ __noinline__ float fix_pixel(const float* pb, float T0, float T1, float T2) {
    float best = -DIST_IND;
    float q0 = 0.f, q1 = 0.f, q2 = 0.f, pv = 0.f;
    float s0 = 0.f, s1 = 0.f, s2 = 0.f;
    int   f  = 0;
#pragma unroll 1
    for (int y = 0; y < Y_; ++y) {
        float u = __ldg(pb + (size_t)y * HW_);
        if (y >= 2 && y <= Y_ - 2) {
            float d = u - pv;
            if (d < best) { best = d; f = y; s0 = q0; s1 = q1; s2 = q2; }
        }
        q0 += u;
        q1 = fmaf((float)y, u, q1);
        q2 = fmaf(u, u, q2);
        pv = u;
    }
    if (f == 0) return 0.f;
    float delta = -seg32(T0, T1, T2);
    float ff    = (float)f;
    float sy_a  = T0 - s0;
    float sxy_a = (T1 - s1) - ff * sy_a;
    float syy_a = T2 - s2;
    delta += seg_gen(f, s0, s1, s2);
    delta += seg_gen(Y_ - f, sy_a, sxy_a, syy_a);
    return delta;
}

__global__ void __launch_bounds__(THREADS, 4)
disturbance_loss_fused(const float* __restrict__ out, float* __restrict__ d_out) {
    const int tid = threadIdx.x;
    float contrib = 0.f;

    if (blockIdx.x < NBLK_A) {
        // ---------- resident path: v8 evict_last, PPT=8, DEPTH=2 ----------
        const int p8 = (blockIdx.x * THREADS + tid) * PPT_A;
        const int b  = p8 >> 16;
        const int hw = p8 & (HW_ - 1);
        const float* __restrict__ base = out + (size_t)b * (Y_ * HW_) + hw;

        float A0[PPT_A], A1[PPT_A], A2[PPT_A], prev[PPT_A];
#pragma unroll
        for (int k = 0; k < PPT_A; ++k) { A0[k] = A1[k] = A2[k] = 0.f; prev[k] = 0.f; }
        float dmin = 0.f;

        float buf[2][PPT_A];
        ldg_el8(base, buf[0]);
        ldg_el8(base + HW_, buf[1]);
#pragma unroll
        for (int y = 0; y < Y_; ++y) {
            const int s = y & 1;
            const float yf = (float)y;
#pragma unroll
            for (int k = 0; k < PPT_A; ++k) {
                const float u = buf[s][k];
                if (y >= 2 && y <= Y_ - 2)
                    dmin = fminf(dmin, u - prev[k]);
                A0[k] += u;
                A1[k] = fmaf(yf, u, A1[k]);
                A2[k] = fmaf(u, u, A2[k]);
                prev[k] = u;
            }
            if (y + 2 < Y_)
                ldg_el8(base + (size_t)(y + 2) * HW_, buf[s]);
        }

#pragma unroll
        for (int k = 0; k < PPT_A; ++k)
            contrib += seg32(A0[k], A1[k], A2[k]);

        if (__ballot_sync(0xFFFFFFFFu, dmin < -DIST_IND)) {
            if (dmin < -DIST_IND) {
#pragma unroll 1
                for (int px = 0; px < PPT_A; ++px)
                    contrib += fix_pixel(base + px, A0[px], A1[px], A2[px]);
            }
        }
    } else {
        // ---------- streaming path: float4 normal loads, PPT=4, DEPTH=4 ----------
        const int p4 = NPIX_A + ((blockIdx.x - NBLK_A) * THREADS + tid) * PPT_B;
        const int b  = p4 >> 16;
        const int hw = p4 & (HW_ - 1);
        const float* __restrict__ basef = out + (size_t)b * (Y_ * HW_) + hw;
        const float4* __restrict__ base4 = (const float4*)basef;
        const int rs = HW_ / 4;

        float A0[PPT_B], A1[PPT_B], A2[PPT_B], prev[PPT_B];
#pragma unroll
        for (int k = 0; k < PPT_B; ++k) { A0[k] = A1[k] = A2[k] = 0.f; prev[k] = 0.f; }
        float dmin = 0.f;

        float4 buf[4];
#pragma unroll
        for (int i = 0; i < 4; ++i) buf[i] = __ldg(&base4[i * rs]);
#pragma unroll
        for (int y = 0; y < Y_; ++y) {
            const int s = y & 3;
            const float yf = (float)y;
            float u[PPT_B] = {buf[s].x, buf[s].y, buf[s].z, buf[s].w};
#pragma unroll
            for (int k = 0; k < PPT_B; ++k) {
                if (y >= 2 && y <= Y_ - 2)
                    dmin = fminf(dmin, u[k] - prev[k]);
                A0[k] += u[k];
                A1[k] = fmaf(yf, u[k], A1[k]);
                A2[k] = fmaf(u[k], u[k], A2[k]);
                prev[k] = u[k];
            }
            if (y + 4 < Y_)
                buf[s] = __ldg(&base4[(y + 4) * rs]);
        }

#pragma unroll
        for (int k = 0; k < PPT_B; ++k)
            contrib += seg32(A0[k], A1[k], A2[k]);

        if (__ballot_sync(0xFFFFFFFFu, dmin < -DIST_IND)) {
            if (dmin < -DIST_IND) {
#pragma unroll 1
                for (int px = 0; px < PPT_B; ++px)
                    contrib += fix_pixel(basef + px, A0[px], A1[px], A2[px]);
            }
        }
    }

    // ---- deterministic in-block reduction ----
    const unsigned lane = tid & 31u;
    const unsigned wid  = tid >> 5;
    float w = contrib;
#pragma unroll
    for (int o = 16; o > 0; o >>= 1)
        w += __shfl_down_sync(0xFFFFFFFFu, w, o);

    __shared__ float warpsum[THREADS / 32];
    if (lane == 0) warpsum[wid] = w;
    __syncthreads();

    __shared__ bool is_last;
    if (wid == 0) {
        float x = (lane < THREADS / 32) ? warpsum[lane] : 0.f;
#pragma unroll
        for (int o = 4; o > 0; o >>= 1)
            x += __shfl_down_sync(0xFFFFFFFFu, x, o);
        if (lane == 0) {
            g_partials[blockIdx.x] = (double)x;
            __threadfence();
            unsigned done = atomicAdd(&g_count, 1u);
            is_last = (done == (unsigned)(GRID - 1));
        }
    }
    __syncthreads();

    // ---- last block sums all partials in fixed index order (deterministic) ----
    if (is_last) {
        __threadfence();
        double sd = 0.0;
        for (int i = tid; i < GRID; i += THREADS)
            sd += g_partials[i];
#pragma unroll
        for (int o = 16; o > 0; o >>= 1)
            sd += __shfl_down_sync(0xFFFFFFFFu, sd, o);
        __shared__ double wsum[THREADS / 32];
        if (lane == 0) wsum[wid] = sd;
        __syncthreads();
        if (wid == 0) {
            double u = (lane < THREADS / 32) ? wsum[lane] : 0.0;
#pragma unroll
            for (int o = 4; o > 0; o >>= 1)
                u += __shfl_down_sync(0xFFFFFFFFu, u, o);
            if (lane == 0) {
                d_out[0] = (float)(u / ((double)Y_ * (double)NPIX));
                g_count = 0;   // reset for next graph replay
            }
        }
    }
}

extern "C" void kernel_launch(void* const* d_in, const int* in_sizes, int n_in,
                              void* d_out, int out_size) {
    const float* out = (const float*)d_in[0];   // 'target' (d_in[1]) unused by reference
    (void)in_sizes; (void)n_in; (void)out_size;
    disturbance_loss_fused<<<GRID, THREADS>>>(out, (float*)d_out);
}

// round 17
// speedup vs baseline: 1.0054x; 1.0054x over previous
#include <cuda_runtime.h>
#include <cstdint>

// Problem shape (fixed by reference setup_inputs)
#define B_   16
#define Y_   32
#define HW_  65536                   // H*W = 256*256
#define NPIX (B_ * HW_)              // 1048576
#define THREADS 256
#define PPT 8                        // pixels per thread (two float4 per row)
#define GRID (NPIX / (THREADS * PPT))  // 512 blocks -> single resident wave
#define DIST_IND 7.0f

__device__ double g_partials[GRID];
__device__ unsigned int g_count = 0;

// Residual for the dominant f=0 case: one segment, n=32 (constants exact).
__device__ __forceinline__ float seg32(float sy, float sxy, float syy) {
    float cov = sxy - 15.5f * sy;                 // sx*sy/n, sx=496, n=32
    float sl  = fminf(fmaxf(cov * (1.f / 2728.f), 0.f), 2.f);
    float c   = (sy - sl * 496.f) * 0.03125f;
    return syy - 2.f * sl * sxy - 2.f * c * sy
         + sl * sl * 10416.f + 2.f * sl * c * 496.f + c * c * 32.f;
}

// Exact general-segment residual (rare slow path; matches reference).
__device__ __noinline__ float seg_gen(int n, float sy, float sxy, float syy) {
    if (n < 3) return 0.f;
    float nf  = (float)n;
    float sx  = 0.5f * nf * (nf - 1.f);
    float sxx = (nf - 1.f) * nf * (2.f * nf - 1.f) * (1.f / 6.f);
    float cov = sxy - sx * sy / nf;
    float var = sxx - sx * sx / nf;
    float vs  = (var > 0.f) ? var : 1.f;
    float sl  = fminf(fmaxf(cov / vs, 0.f), 2.f);
    float c   = (sy - sl * sx) / nf;
    return syy - 2.f * sl * sxy - 2.f * c * sy
         + sl * sl * sxx + 2.f * sl * c * sx + c * c * nf;
}

// Exact per-pixel correction: rescan column, replace f=0 value if f>0.
__device__ __noinline__ float fix_pixel(const float* pb, float T0, float T1, float T2) {
    float best = -DIST_IND;
    float q0 = 0.f, q1 = 0.f, q2 = 0.f, pv = 0.f;
    float s0 = 0.f, s1 = 0.f, s2 = 0.f;
    int   f  = 0;
#pragma unroll 1
    for (int y = 0; y < Y_; ++y) {
        float u = __ldg(pb + (size_t)y * HW_);
        if (y >= 2 && y <= Y_ - 2) {
            float d = u - pv;
            if (d < best) { best = d; f = y; s0 = q0; s1 = q1; s2 = q2; }
        }
        q0 += u;
        q1 = fmaf((float)y, u, q1);
        q2 = fmaf(u, u, q2);
        pv = u;
    }
    if (f == 0) return 0.f;
    float delta = -seg32(T0, T1, T2);
    float ff    = (float)f;
    float sy_a  = T0 - s0;
    float sxy_a = (T1 - s1) - ff * sy_a;
    float syy_a = T2 - s2;
    delta += seg_gen(f, s0, s1, s2);
    delta += seg_gen(Y_ - f, sy_a, sxy_a, syy_a);
    return delta;
}

__global__ void __launch_bounds__(THREADS, 4)
disturbance_loss_fused(const float* __restrict__ out, float* __restrict__ d_out) {
    const int tid = threadIdx.x;
    const int p8  = (blockIdx.x * THREADS + tid) * PPT;  // 8 adjacent pixels, 32B aligned
    const int b   = p8 >> 16;
    const int hw  = p8 & (HW_ - 1);
    const float*  __restrict__ base  = out + (size_t)b * (Y_ * HW_) + hw;
    const float4* __restrict__ base4 = (const float4*)base;
    const int rs4 = HW_ / 4;                             // row stride in float4

    float A0[PPT], A1[PPT], A2[PPT], prev[PPT];
#pragma unroll
    for (int k = 0; k < PPT; ++k) { A0[k] = A1[k] = A2[k] = 0.f; prev[k] = 0.f; }
    float dmin = 0.f;                                    // min interior diff over 8 px

    // Double-buffered rows; whole chip marches y together (single resident wave,
    // linear block->pixel map => concurrent footprint is ~one y-plane per image).
    float4 ba[2], bb[2];
    ba[0] = __ldg(&base4[0]);          bb[0] = __ldg(&base4[1]);
    ba[1] = __ldg(&base4[rs4]);        bb[1] = __ldg(&base4[rs4 + 1]);

#pragma unroll
    for (int y = 0; y < Y_; ++y) {
        const int s = y & 1;
        const float yf = (float)y;
        float u[PPT] = {ba[s].x, ba[s].y, ba[s].z, ba[s].w,
                        bb[s].x, bb[s].y, bb[s].z, bb[s].w};
        // Prefetch y+2 into the slot we just consumed (before the math).
        if (y + 2 < Y_) {
            ba[s] = __ldg(&base4[(y + 2) * rs4]);
            bb[s] = __ldg(&base4[(y + 2) * rs4 + 1]);
        }
#pragma unroll
        for (int k = 0; k < PPT; ++k) {
            if (y >= 2 && y <= Y_ - 2)
                dmin = fminf(dmin, u[k] - prev[k]);
            A0[k] += u[k];
            A1[k] = fmaf(yf, u[k], A1[k]);
            A2[k] = fmaf(u[k], u[k], A2[k]);
            prev[k] = u[k];
        }
    }

    // Fast-path contribution: f=0 for every pixel (true except ~4e-7/elem).
    float contrib = 0.f;
#pragma unroll
    for (int k = 0; k < PPT; ++k)
        contrib += seg32(A0[k], A1[k], A2[k]);

    // Rare exact correction.
    if (__ballot_sync(0xFFFFFFFFu, dmin < -DIST_IND)) {
        if (dmin < -DIST_IND) {
#pragma unroll 1
            for (int px = 0; px < PPT; ++px)
                contrib += fix_pixel(base + px, A0[px], A1[px], A2[px]);
        }
    }

    // ---- deterministic in-block reduction ----
    const unsigned lane = tid & 31u;
    const unsigned wid  = tid >> 5;
    float w = contrib;
#pragma unroll
    for (int o = 16; o > 0; o >>= 1)
        w += __shfl_down_sync(0xFFFFFFFFu, w, o);

    __shared__ float warpsum[THREADS / 32];
    if (lane == 0) warpsum[wid] = w;
    __syncthreads();

    __shared__ bool is_last;
    if (wid == 0) {
        float x = (lane < THREADS / 32) ? warpsum[lane] : 0.f;
#pragma unroll
        for (int o = 4; o > 0; o >>= 1)
            x += __shfl_down_sync(0xFFFFFFFFu, x, o);
        if (lane == 0) {
            g_partials[blockIdx.x] = (double)x;
            __threadfence();
            unsigned done = atomicAdd(&g_count, 1u);
            is_last = (done == (unsigned)(GRID - 1));
        }
    }
    __syncthreads();

    // ---- last block sums all partials in fixed index order (deterministic) ----
    if (is_last) {
        __threadfence();
        double sd = 0.0;
#pragma unroll
        for (int k = 0; k < GRID / THREADS; ++k)
            sd += g_partials[tid + k * THREADS];
#pragma unroll
        for (int o = 16; o > 0; o >>= 1)
            sd += __shfl_down_sync(0xFFFFFFFFu, sd, o);
        __shared__ double wsum[THREADS / 32];
        if (lane == 0) wsum[wid] = sd;
        __syncthreads();
        if (wid == 0) {
            double u = (lane < THREADS / 32) ? wsum[lane] : 0.0;
#pragma unroll
            for (int o = 4; o > 0; o >>= 1)
                u += __shfl_down_sync(0xFFFFFFFFu, u, o);
            if (lane == 0) {
                d_out[0] = (float)(u / ((double)Y_ * (double)NPIX));
                g_count = 0;   // reset for next graph replay
            }
        }
    }
}

extern "C" void kernel_launch(void* const* d_in, const int* in_sizes, int n_in,
                              void* d_out, int out_size) {
    const float* out = (const float*)d_in[0];   // 'target' (d_in[1]) unused by reference
    (void)in_sizes; (void)n_in; (void)out_size;
    disturbance_loss_fused<<<GRID, THREADS>>>(out, (float*)d_out);
}